// round 9
// baseline (speedup 1.0000x reference)
#include <cuda_runtime.h>
#include <cstdint>

// ---------------- scratch (device globals; no allocation) ----------------
#define NMAX 50000
#define EMAX 800000
__device__ float g_h1 [NMAX * 128];   // x@W1, later h2 (GAT transform)
__device__ float g_agg[NMAX * 128];   // relu(GCN1) output
__device__ float g_inv[NMAX];         // rsqrt(deg)
__device__ float g_as [NMAX * 2];     // GAT a_src per (node, head)
__device__ float g_ad [NMAX * 2];     // GAT a_dst per (node, head)
__device__ float g_hx [NMAX * 64];    // elu(mean-head GAT) = GCN2 input
__device__ float g_h3 [NMAX * 64];    // hx @ W3
__device__ int   g_deg[NMAX];
__device__ int   g_off[NMAX];
__device__ int   g_cur[NMAX];
__device__ int   g_srcs[EMAX];        // src ids bucketed by dst
__device__ unsigned g_total;

__device__ __forceinline__ float leaky(float v) { return v > 0.f ? v : 0.2f * v; }

// ---------------- degree + CSR build ----------------
__global__ void k_zero_deg(int* deg, unsigned* total, int n) {
    int i = blockIdx.x * blockDim.x + threadIdx.x;
    if (i < n) deg[i] = 0;
    if (i == 0) *total = 0u;
}
__global__ void k_deg_count(const int* __restrict__ dst, int* deg, int E) {
    int i = blockIdx.x * blockDim.x + threadIdx.x;
    if (i < E) atomicAdd(&deg[dst[i]], 1);
}
__global__ void k_offsets(const int* __restrict__ deg, int* off, int* cur,
                          float* inv, unsigned* total, int n) {
    int i = blockIdx.x * blockDim.x + threadIdx.x;
    int lane = threadIdx.x & 31;
    int d = (i < n) ? deg[i] : 0;
    int x = d;
    #pragma unroll
    for (int o = 1; o < 32; o <<= 1) {
        int y = __shfl_up_sync(0xffffffffu, x, o);
        if (lane >= o) x += y;
    }
    int wsum = __shfl_sync(0xffffffffu, x, 31);
    unsigned base = 0;
    if (lane == 31) base = atomicAdd(total, (unsigned)wsum);
    base = __shfl_sync(0xffffffffu, base, 31);
    int excl = (int)base + x - d;
    if (i < n) {
        off[i] = excl; cur[i] = excl;
        inv[i] = rsqrtf((float)(d + 1));
    }
}
__global__ void k_fill(const int* __restrict__ src, const int* __restrict__ dst,
                       int* cur, int* srcs, int E) {
    int base = (blockIdx.x * blockDim.x + threadIdx.x) * 4;
    #pragma unroll
    for (int j = 0; j < 4; j++) {
        int i = base + j;
        if (i < E) {
            int pos = atomicAdd(&cur[dst[i]], 1);
            srcs[pos] = src[i];
        }
    }
}

// ---------------- TF32 tensor-core GEMM with error compensation ----------------
__device__ __forceinline__ void split_tf32(float x, uint32_t& hi, uint32_t& lo) {
    uint32_t h;
    asm("cvt.rna.tf32.f32 %0, %1;" : "=r"(h) : "f"(x));
    float l = x - __uint_as_float(h);
    uint32_t lw;
    asm("cvt.rna.tf32.f32 %0, %1;" : "=r"(lw) : "f"(l));
    hi = h; lo = lw;
}
__device__ __forceinline__ void mma_tf32(float* c, const uint32_t* a, const uint32_t* b) {
    asm volatile("mma.sync.aligned.m16n8k8.row.col.f32.tf32.tf32.f32 "
        "{%0,%1,%2,%3},{%4,%5,%6,%7},{%8,%9},{%0,%1,%2,%3};"
        : "+f"(c[0]), "+f"(c[1]), "+f"(c[2]), "+f"(c[3])
        : "r"(a[0]), "r"(a[1]), "r"(a[2]), "r"(a[3]), "r"(b[0]), "r"(b[1]));
}

template<int K, int P>
__global__ void __launch_bounds__(256)
gemm_tf32(const float* __restrict__ X, const float* __restrict__ W,
          float* __restrict__ Y, int n)
{
    constexpr int BM = 128;
    constexpr int BK = 32;
    constexpr int WARPS_N = P / 64;
    constexpr int WARPS_M = 8 / WARPS_N;
    constexpr int WM = BM / WARPS_M;
    constexpr int MF = WM / 16;
    constexpr int NF = 8;
    constexpr int XS = BK + 4;
    constexpr int WS = P + 8;

    __shared__ __align__(16) float Xs[BM * XS];
    __shared__ __align__(16) float Ws[BK * WS];

    int tid = threadIdx.x;
    int wid = tid >> 5, lane = tid & 31;
    int wm = wid % WARPS_M, wn = wid / WARPS_M;
    int g = lane >> 2, tg = lane & 3;

    int r0 = blockIdx.x * BM;
    int rows = n - r0; if (rows > BM) rows = BM;

    float c[MF][NF][4];
    #pragma unroll
    for (int mf = 0; mf < MF; mf++)
        #pragma unroll
        for (int nf = 0; nf < NF; nf++)
            #pragma unroll
            for (int q = 0; q < 4; q++) c[mf][nf][q] = 0.f;

    for (int kt = 0; kt < K; kt += BK) {
        #pragma unroll
        for (int i = tid; i < BK * P / 4; i += 256) {
            int k = i / (P / 4), c4 = (i % (P / 4)) * 4;
            *(float4*)&Ws[k * WS + c4] = *(const float4*)&W[(kt + k) * P + c4];
        }
        #pragma unroll
        for (int i = tid; i < BM * BK / 4; i += 256) {
            int r = i / (BK / 4), k4 = (i % (BK / 4)) * 4;
            float4 v = (r < rows) ? *(const float4*)&X[(size_t)(r0 + r) * K + kt + k4]
                                  : make_float4(0.f, 0.f, 0.f, 0.f);
            *(float4*)&Xs[r * XS + k4] = v;
        }
        __syncthreads();
        #pragma unroll
        for (int k8 = 0; k8 < BK; k8 += 8) {
            uint32_t ah[MF][4], al[MF][4];
            #pragma unroll
            for (int mf = 0; mf < MF; mf++) {
                int rb = wm * WM + mf * 16;
                split_tf32(Xs[(rb + g    ) * XS + k8 + tg    ], ah[mf][0], al[mf][0]);
                split_tf32(Xs[(rb + g + 8) * XS + k8 + tg    ], ah[mf][1], al[mf][1]);
                split_tf32(Xs[(rb + g    ) * XS + k8 + tg + 4], ah[mf][2], al[mf][2]);
                split_tf32(Xs[(rb + g + 8) * XS + k8 + tg + 4], ah[mf][3], al[mf][3]);
            }
            uint32_t bh[NF][2], bl[NF][2];
            #pragma unroll
            for (int nf = 0; nf < NF; nf++) {
                int col = wn * 64 + nf * 8 + g;
                split_tf32(Ws[(k8 + tg    ) * WS + col], bh[nf][0], bl[nf][0]);
                split_tf32(Ws[(k8 + tg + 4) * WS + col], bh[nf][1], bl[nf][1]);
            }
            #pragma unroll
            for (int mf = 0; mf < MF; mf++)
                #pragma unroll
                for (int nf = 0; nf < NF; nf++) {
                    mma_tf32(c[mf][nf], ah[mf], bh[nf]);
                    mma_tf32(c[mf][nf], ah[mf], bl[nf]);
                    mma_tf32(c[mf][nf], al[mf], bh[nf]);
                }
        }
        __syncthreads();
    }
    #pragma unroll
    for (int mf = 0; mf < MF; mf++) {
        int rb = wm * WM + mf * 16;
        #pragma unroll
        for (int nf = 0; nf < NF; nf++) {
            int col = wn * 64 + nf * 8 + 2 * tg;
            int ra = rb + g, rc = rb + g + 8;
            if (ra < rows)
                *(float2*)&Y[(size_t)(r0 + ra) * P + col] = make_float2(c[mf][nf][0], c[mf][nf][1]);
            if (rc < rows)
                *(float2*)&Y[(size_t)(r0 + rc) * P + col] = make_float2(c[mf][nf][2], c[mf][nf][3]);
        }
    }
}

// ---------------- GCN1 pull-aggregation: 4 warps/node, 1 feat/lane, unroll-8 ----------------
__global__ void k_gcn1_agg(const float* __restrict__ h, const int* __restrict__ off,
                           const int* __restrict__ deg, const int* __restrict__ srcs,
                           const float* __restrict__ inv, const float* __restrict__ bias,
                           float* __restrict__ out, int n)
{
    int gid = blockIdx.x * blockDim.x + threadIdx.x;
    int w = gid >> 5, lane = gid & 31;
    int d = w >> 2, ws = w & 3;
    if (d >= n) return;
    int f = ws * 32 + lane;
    int beg = off[d], end = beg + deg[d];
    float invd = inv[d];

    float acc = h[(size_t)d * 128 + f] * invd * invd;

    int i = beg;
    for (; i + 8 <= end; i += 8) {
        float a0=0,a1=0,a2=0,a3=0,a4=0,a5=0,a6=0,a7=0;
        #pragma unroll
        for (int j = 0; j < 8; j++) {
            int s = srcs[i + j];
            float c = inv[s] * invd;
            float v = h[(size_t)s * 128 + f];
            switch (j) {
                case 0: a0 = v * c; break; case 1: a1 = v * c; break;
                case 2: a2 = v * c; break; case 3: a3 = v * c; break;
                case 4: a4 = v * c; break; case 5: a5 = v * c; break;
                case 6: a6 = v * c; break; case 7: a7 = v * c; break;
            }
        }
        acc += ((a0 + a1) + (a2 + a3)) + ((a4 + a5) + (a6 + a7));
    }
    for (; i < end; i++) {
        int s = srcs[i];
        acc += h[(size_t)s * 128 + f] * (inv[s] * invd);
    }
    out[(size_t)d * 128 + f] = fmaxf(acc + bias[f], 0.f);
}

// ---------------- GAT scores ----------------
__global__ void k_gat_scores(const float* __restrict__ h2, const float* __restrict__ att_s,
                             const float* __restrict__ att_d, float* __restrict__ as_,
                             float* __restrict__ ad_, int n)
{
    int gid = blockIdx.x * blockDim.x + threadIdx.x;
    int w = gid >> 5, lane = gid & 31;
    if (w >= n * 2) return;
    int nn = w >> 1, hh = w & 1;
    const float* row = h2 + (size_t)nn * 128 + hh * 64;
    float v0 = row[lane], v1 = row[lane + 32];
    float s = v0 * att_s[hh * 64 + lane] + v1 * att_s[hh * 64 + lane + 32];
    float d = v0 * att_d[hh * 64 + lane] + v1 * att_d[hh * 64 + lane + 32];
    #pragma unroll
    for (int o = 16; o; o >>= 1) {
        s += __shfl_down_sync(0xffffffffu, s, o);
        d += __shfl_down_sync(0xffffffffu, d, o);
    }
    if (lane == 0) { as_[w] = s; ad_[w] = d; }
}

// ---------------- GAT fused softmax + aggregation: one 128-thread block per node ----------
// warp ws handles head0 feats [16ws,16ws+16) on lanes 0-15 and head1 feats
// 64+[16ws,16ws+16) on lanes 16-31; head-mean via shfl_down 16.
__global__ void __launch_bounds__(128)
k_gat_agg(const float* __restrict__ h2, const int* __restrict__ off,
          const int* __restrict__ deg, const int* __restrict__ srcs,
          const float* __restrict__ as_, const float* __restrict__ ad_,
          const float* __restrict__ bg, float* __restrict__ hx, int n)
{
    __shared__ float sm0[4], sm1[4], sd0[4], sd1[4];
    int d = blockIdx.x;
    if (d >= n) return;
    int tid = threadIdx.x;
    int ws = tid >> 5, lane = tid & 31;
    int beg = off[d], end = beg + deg[d];

    float2 ad = *(const float2*)(ad_ + d * 2);
    float2 asd = *(const float2*)(as_ + d * 2);
    float e0s = leaky(asd.x + ad.x), e1s = leaky(asd.y + ad.y);

    // pass 1: max (block-strided, block reduce)
    float m0 = e0s, m1 = e1s;
    for (int i = beg + tid; i < end; i += 128) {
        float2 a = *(const float2*)(as_ + srcs[i] * 2);
        m0 = fmaxf(m0, leaky(a.x + ad.x));
        m1 = fmaxf(m1, leaky(a.y + ad.y));
    }
    #pragma unroll
    for (int o = 16; o; o >>= 1) {
        m0 = fmaxf(m0, __shfl_xor_sync(0xffffffffu, m0, o));
        m1 = fmaxf(m1, __shfl_xor_sync(0xffffffffu, m1, o));
    }
    if (lane == 0) { sm0[ws] = m0; sm1[ws] = m1; }
    __syncthreads();
    m0 = fmaxf(fmaxf(sm0[0], sm0[1]), fmaxf(sm0[2], sm0[3]));
    m1 = fmaxf(fmaxf(sm1[0], sm1[1]), fmaxf(sm1[2], sm1[3]));

    // pass 2: denominator (block-strided, block reduce)
    float den0 = 0.f, den1 = 0.f;
    for (int i = beg + tid; i < end; i += 128) {
        float2 a = *(const float2*)(as_ + srcs[i] * 2);
        den0 += __expf(leaky(a.x + ad.x) - m0);
        den1 += __expf(leaky(a.y + ad.y) - m1);
    }
    #pragma unroll
    for (int o = 16; o; o >>= 1) {
        den0 += __shfl_xor_sync(0xffffffffu, den0, o);
        den1 += __shfl_xor_sync(0xffffffffu, den1, o);
    }
    if (lane == 0) { sd0[ws] = den0; sd1[ws] = den1; }
    __syncthreads();
    den0 = sd0[0] + sd0[1] + sd0[2] + sd0[3] + __expf(e0s - m0);
    den1 = sd1[0] + sd1[1] + sd1[2] + sd1[3] + __expf(e1s - m1);
    float r0 = __fdividef(1.f, den0), r1 = __fdividef(1.f, den1);

    // pass 3: feature aggregation; each warp covers all edges for its slice
    bool head0 = lane < 16;
    int f0 = ws * 16 + (lane & 15);                 // output feature [0,64)
    int fi = head0 ? f0 : 64 + f0;                  // h2 feature index
    float als = head0 ? __expf(e0s - m0) * r0 : __expf(e1s - m1) * r1;
    float acc = h2[(size_t)d * 128 + fi] * als;

    int i = beg;
    for (; i + 4 <= end; i += 4) {
        int s0 = srcs[i], s1 = srcs[i+1], s2 = srcs[i+2], s3 = srcs[i+3];
        float2 a0 = *(const float2*)(as_ + s0 * 2);
        float2 a1 = *(const float2*)(as_ + s1 * 2);
        float2 a2 = *(const float2*)(as_ + s2 * 2);
        float2 a3 = *(const float2*)(as_ + s3 * 2);
        float c0 = head0 ? __expf(leaky(a0.x + ad.x) - m0) * r0 : __expf(leaky(a0.y + ad.y) - m1) * r1;
        float c1 = head0 ? __expf(leaky(a1.x + ad.x) - m0) * r0 : __expf(leaky(a1.y + ad.y) - m1) * r1;
        float c2 = head0 ? __expf(leaky(a2.x + ad.x) - m0) * r0 : __expf(leaky(a2.y + ad.y) - m1) * r1;
        float c3 = head0 ? __expf(leaky(a3.x + ad.x) - m0) * r0 : __expf(leaky(a3.y + ad.y) - m1) * r1;
        float v0 = h2[(size_t)s0 * 128 + fi];
        float v1 = h2[(size_t)s1 * 128 + fi];
        float v2 = h2[(size_t)s2 * 128 + fi];
        float v3 = h2[(size_t)s3 * 128 + fi];
        acc += (v0 * c0 + v1 * c1) + (v2 * c2 + v3 * c3);
    }
    for (; i < end; i++) {
        int s = srcs[i];
        float2 a = *(const float2*)(as_ + s * 2);
        float c = head0 ? __expf(leaky(a.x + ad.x) - m0) * r0
                        : __expf(leaky(a.y + ad.y) - m1) * r1;
        acc += h2[(size_t)s * 128 + fi] * c;
    }
    // head mean + bias + elu
    float other = __shfl_down_sync(0xffffffffu, acc, 16);
    if (head0) {
        float r = 0.5f * (acc + other) + bg[f0];
        hx[(size_t)d * 64 + f0] = r > 0.f ? r : expm1f(r);
    }
}

// ---------------- GCN2 pull-aggregation: 2 warps/node, 1 feat/lane, unroll-8 ----------------
__global__ void k_gcn2_agg(const float* __restrict__ h, const int* __restrict__ off,
                           const int* __restrict__ deg, const int* __restrict__ srcs,
                           const float* __restrict__ inv, const float* __restrict__ bias,
                           float* __restrict__ out, int n)
{
    int gid = blockIdx.x * blockDim.x + threadIdx.x;
    int w = gid >> 5, lane = gid & 31;
    int d = w >> 1, ws = w & 1;
    if (d >= n) return;
    int f = ws * 32 + lane;
    int beg = off[d], end = beg + deg[d];
    float invd = inv[d];

    float acc = h[(size_t)d * 64 + f] * invd * invd;

    int i = beg;
    for (; i + 8 <= end; i += 8) {
        float a0=0,a1=0,a2=0,a3=0,a4=0,a5=0,a6=0,a7=0;
        #pragma unroll
        for (int j = 0; j < 8; j++) {
            int s = srcs[i + j];
            float c = inv[s] * invd;
            float v = h[(size_t)s * 64 + f];
            switch (j) {
                case 0: a0 = v * c; break; case 1: a1 = v * c; break;
                case 2: a2 = v * c; break; case 3: a3 = v * c; break;
                case 4: a4 = v * c; break; case 5: a5 = v * c; break;
                case 6: a6 = v * c; break; case 7: a7 = v * c; break;
            }
        }
        acc += ((a0 + a1) + (a2 + a3)) + ((a4 + a5) + (a6 + a7));
    }
    for (; i < end; i++) {
        int s = srcs[i];
        acc += h[(size_t)s * 64 + f] * (inv[s] * invd);
    }
    out[(size_t)d * 64 + f] = acc + bias[f];
}

// ---------------- host ----------------
static inline int up(int a, int b) { return (a + b - 1) / b; }

extern "C" void kernel_launch(void* const* d_in, const int* in_sizes, int n_in,
                              void* d_out, int out_size)
{
    const float* x       = (const float*)d_in[0];
    const int*   ei      = (const int*)d_in[1];    // int32 (JAX x64 disabled)
    const float* W1      = (const float*)d_in[2];
    const float* b1      = (const float*)d_in[3];
    const float* Wg      = (const float*)d_in[4];
    const float* att_src = (const float*)d_in[5];
    const float* att_dst = (const float*)d_in[6];
    const float* bg      = (const float*)d_in[7];
    const float* W3      = (const float*)d_in[8];
    const float* b3      = (const float*)d_in[9];
    float* out = (float*)d_out;

    int n = in_sizes[0] / 128;
    int E = in_sizes[1] / 2;
    const int* src = ei;
    const int* dst = ei + E;

    void* p;
    cudaGetSymbolAddress(&p, g_h1);   float* h1    = (float*)p;
    cudaGetSymbolAddress(&p, g_agg);  float* agg   = (float*)p;
    cudaGetSymbolAddress(&p, g_inv);  float* inv   = (float*)p;
    cudaGetSymbolAddress(&p, g_as);   float* as_   = (float*)p;
    cudaGetSymbolAddress(&p, g_ad);   float* ad_   = (float*)p;
    cudaGetSymbolAddress(&p, g_hx);   float* hx    = (float*)p;
    cudaGetSymbolAddress(&p, g_h3);   float* h3    = (float*)p;
    cudaGetSymbolAddress(&p, g_deg);  int*   deg   = (int*)p;
    cudaGetSymbolAddress(&p, g_off);  int*   off   = (int*)p;
    cudaGetSymbolAddress(&p, g_cur);  int*   cur   = (int*)p;
    cudaGetSymbolAddress(&p, g_srcs); int*   srcs  = (int*)p;
    cudaGetSymbolAddress(&p, g_total); unsigned* total = (unsigned*)p;

    // fork-join side stream for CSR build (created once; capture-safe pattern)
    static cudaStream_t s2 = nullptr;
    static cudaEvent_t evFork = nullptr, evJoin = nullptr;
    if (!s2) {
        cudaStreamCreateWithFlags(&s2, cudaStreamNonBlocking);
        cudaEventCreateWithFlags(&evFork, cudaEventDisableTiming);
        cudaEventCreateWithFlags(&evJoin, cudaEventDisableTiming);
    }

    const int T = 256;

    // ---- fork: CSR build on s2, GEMM1 on default ----
    cudaEventRecord(evFork, 0);
    cudaStreamWaitEvent(s2, evFork, 0);

    k_zero_deg <<<up(n, T), T, 0, s2>>>(deg, total, n);
    k_deg_count<<<up(E, T), T, 0, s2>>>(dst, deg, E);
    k_offsets  <<<up(n, T), T, 0, s2>>>(deg, off, cur, inv, total, n);
    k_fill     <<<up(E, T * 4), T, 0, s2>>>(src, dst, cur, srcs, E);
    cudaEventRecord(evJoin, s2);

    gemm_tf32<128,128><<<up(n, 128), 256>>>(x, W1, h1, n);

    cudaStreamWaitEvent(0, evJoin, 0);   // join before first aggregation

    // ---- GCN layer 1 ----
    k_gcn1_agg<<<up(n * 128, T), T>>>(h1, off, deg, srcs, inv, b1, agg, n);

    // ---- GAT layer ----
    gemm_tf32<128,128><<<up(n, 128), 256>>>(agg, Wg, h1, n);   // h2 in h1
    k_gat_scores<<<up(n * 64, T), T>>>(h1, att_src, att_dst, as_, ad_, n);
    k_gat_agg   <<<n, 128>>>(h1, off, deg, srcs, as_, ad_, bg, hx, n);

    // ---- GCN layer 2 ----
    gemm_tf32<64,64><<<up(n, 128), 256>>>(hx, W3, h3, n);
    k_gcn2_agg<<<up(n * 64, T), T>>>(h3, off, deg, srcs, inv, b3, out, n);
}

// round 10
// speedup vs baseline: 1.6120x; 1.6120x over previous
#include <cuda_runtime.h>
#include <cstdint>

// ---------------- scratch (device globals; no allocation) ----------------
#define NMAX 50000
#define EMAX 800000
__device__ float g_h1 [NMAX * 128];   // x@W1, later h2 (GAT transform)
__device__ float g_agg[NMAX * 128];   // relu(GCN1) output
__device__ float g_inv[NMAX];         // rsqrt(deg)
__device__ float g_as [NMAX * 2];     // GAT a_src per (node, head)
__device__ float g_ad [NMAX * 2];     // GAT a_dst per (node, head)
__device__ float g_hx [NMAX * 64];    // elu(mean-head GAT) = GCN2 input
__device__ float g_h3 [NMAX * 64];    // hx @ W3
__device__ int   g_deg[NMAX];
__device__ int   g_off[NMAX];
__device__ int   g_cur[NMAX];
__device__ int   g_srcs[EMAX];        // src ids bucketed by dst
__device__ unsigned g_total;

__device__ __forceinline__ float leaky(float v) { return v > 0.f ? v : 0.2f * v; }

// ---------------- degree + CSR build ----------------
__global__ void k_zero_deg(int* deg, unsigned* total, int n) {
    int i = blockIdx.x * blockDim.x + threadIdx.x;
    if (i < n) deg[i] = 0;
    if (i == 0) *total = 0u;
}
__global__ void k_deg_count(const int* __restrict__ dst, int* deg, int E) {
    int i = blockIdx.x * blockDim.x + threadIdx.x;
    if (i < E) atomicAdd(&deg[dst[i]], 1);
}
__global__ void k_offsets(const int* __restrict__ deg, int* off, int* cur,
                          float* inv, unsigned* total, int n) {
    int i = blockIdx.x * blockDim.x + threadIdx.x;
    int lane = threadIdx.x & 31;
    int d = (i < n) ? deg[i] : 0;
    int x = d;
    #pragma unroll
    for (int o = 1; o < 32; o <<= 1) {
        int y = __shfl_up_sync(0xffffffffu, x, o);
        if (lane >= o) x += y;
    }
    int wsum = __shfl_sync(0xffffffffu, x, 31);
    unsigned base = 0;
    if (lane == 31) base = atomicAdd(total, (unsigned)wsum);
    base = __shfl_sync(0xffffffffu, base, 31);
    int excl = (int)base + x - d;
    if (i < n) {
        off[i] = excl; cur[i] = excl;
        inv[i] = rsqrtf((float)(d + 1));
    }
}
__global__ void k_fill(const int* __restrict__ src, const int* __restrict__ dst,
                       int* cur, int* srcs, int E) {
    int base = (blockIdx.x * blockDim.x + threadIdx.x) * 4;
    #pragma unroll
    for (int j = 0; j < 4; j++) {
        int i = base + j;
        if (i < E) {
            int pos = atomicAdd(&cur[dst[i]], 1);
            srcs[pos] = src[i];
        }
    }
}

// ---------------- TF32 tensor-core GEMM with error compensation ----------------
__device__ __forceinline__ void split_tf32(float x, uint32_t& hi, uint32_t& lo) {
    uint32_t h;
    asm("cvt.rna.tf32.f32 %0, %1;" : "=r"(h) : "f"(x));
    float l = x - __uint_as_float(h);
    uint32_t lw;
    asm("cvt.rna.tf32.f32 %0, %1;" : "=r"(lw) : "f"(l));
    hi = h; lo = lw;
}
__device__ __forceinline__ void mma_tf32(float* c, const uint32_t* a, const uint32_t* b) {
    asm volatile("mma.sync.aligned.m16n8k8.row.col.f32.tf32.tf32.f32 "
        "{%0,%1,%2,%3},{%4,%5,%6,%7},{%8,%9},{%0,%1,%2,%3};"
        : "+f"(c[0]), "+f"(c[1]), "+f"(c[2]), "+f"(c[3])
        : "r"(a[0]), "r"(a[1]), "r"(a[2]), "r"(a[3]), "r"(b[0]), "r"(b[1]));
}

template<int K, int P>
__global__ void __launch_bounds__(256)
gemm_tf32(const float* __restrict__ X, const float* __restrict__ W,
          float* __restrict__ Y, int n)
{
    constexpr int BM = 128;
    constexpr int BK = 32;
    constexpr int WARPS_N = P / 64;
    constexpr int WARPS_M = 8 / WARPS_N;
    constexpr int WM = BM / WARPS_M;
    constexpr int MF = WM / 16;
    constexpr int NF = 8;
    constexpr int XS = BK + 4;
    constexpr int WS = P + 8;

    __shared__ __align__(16) float Xs[BM * XS];
    __shared__ __align__(16) float Ws[BK * WS];

    int tid = threadIdx.x;
    int wid = tid >> 5, lane = tid & 31;
    int wm = wid % WARPS_M, wn = wid / WARPS_M;
    int g = lane >> 2, tg = lane & 3;

    int r0 = blockIdx.x * BM;
    int rows = n - r0; if (rows > BM) rows = BM;

    float c[MF][NF][4];
    #pragma unroll
    for (int mf = 0; mf < MF; mf++)
        #pragma unroll
        for (int nf = 0; nf < NF; nf++)
            #pragma unroll
            for (int q = 0; q < 4; q++) c[mf][nf][q] = 0.f;

    for (int kt = 0; kt < K; kt += BK) {
        #pragma unroll
        for (int i = tid; i < BK * P / 4; i += 256) {
            int k = i / (P / 4), c4 = (i % (P / 4)) * 4;
            *(float4*)&Ws[k * WS + c4] = *(const float4*)&W[(kt + k) * P + c4];
        }
        #pragma unroll
        for (int i = tid; i < BM * BK / 4; i += 256) {
            int r = i / (BK / 4), k4 = (i % (BK / 4)) * 4;
            float4 v = (r < rows) ? *(const float4*)&X[(size_t)(r0 + r) * K + kt + k4]
                                  : make_float4(0.f, 0.f, 0.f, 0.f);
            *(float4*)&Xs[r * XS + k4] = v;
        }
        __syncthreads();
        #pragma unroll
        for (int k8 = 0; k8 < BK; k8 += 8) {
            uint32_t ah[MF][4], al[MF][4];
            #pragma unroll
            for (int mf = 0; mf < MF; mf++) {
                int rb = wm * WM + mf * 16;
                split_tf32(Xs[(rb + g    ) * XS + k8 + tg    ], ah[mf][0], al[mf][0]);
                split_tf32(Xs[(rb + g + 8) * XS + k8 + tg    ], ah[mf][1], al[mf][1]);
                split_tf32(Xs[(rb + g    ) * XS + k8 + tg + 4], ah[mf][2], al[mf][2]);
                split_tf32(Xs[(rb + g + 8) * XS + k8 + tg + 4], ah[mf][3], al[mf][3]);
            }
            uint32_t bh[NF][2], bl[NF][2];
            #pragma unroll
            for (int nf = 0; nf < NF; nf++) {
                int col = wn * 64 + nf * 8 + g;
                split_tf32(Ws[(k8 + tg    ) * WS + col], bh[nf][0], bl[nf][0]);
                split_tf32(Ws[(k8 + tg + 4) * WS + col], bh[nf][1], bl[nf][1]);
            }
            #pragma unroll
            for (int mf = 0; mf < MF; mf++)
                #pragma unroll
                for (int nf = 0; nf < NF; nf++) {
                    mma_tf32(c[mf][nf], ah[mf], bh[nf]);
                    mma_tf32(c[mf][nf], ah[mf], bl[nf]);
                    mma_tf32(c[mf][nf], al[mf], bh[nf]);
                }
        }
        __syncthreads();
    }
    #pragma unroll
    for (int mf = 0; mf < MF; mf++) {
        int rb = wm * WM + mf * 16;
        #pragma unroll
        for (int nf = 0; nf < NF; nf++) {
            int col = wn * 64 + nf * 8 + 2 * tg;
            int ra = rb + g, rc = rb + g + 8;
            if (ra < rows)
                *(float2*)&Y[(size_t)(r0 + ra) * P + col] = make_float2(c[mf][nf][0], c[mf][nf][1]);
            if (rc < rows)
                *(float2*)&Y[(size_t)(r0 + rc) * P + col] = make_float2(c[mf][nf][2], c[mf][nf][3]);
        }
    }
}

// ---------------- GCN1 pull-aggregation (F=128) + relu, warp/node, unroll-8 ----------------
__global__ void k_gcn1_agg(const float* __restrict__ h, const int* __restrict__ off,
                           const int* __restrict__ deg, const int* __restrict__ srcs,
                           const float* __restrict__ inv, const float* __restrict__ bias,
                           float* __restrict__ out, int n)
{
    int gid = blockIdx.x * blockDim.x + threadIdx.x;
    int d = gid >> 5, lane = gid & 31;
    if (d >= n) return;
    int beg = off[d], end = beg + deg[d];
    float invd = inv[d];

    float4 sv = *(const float4*)(h + (size_t)d * 128 + lane * 4);
    float cs = invd * invd;
    float4 acc = make_float4(sv.x * cs, sv.y * cs, sv.z * cs, sv.w * cs);

    int i = beg;
    for (; i + 8 <= end; i += 8) {
        float4 acc2 = make_float4(0.f, 0.f, 0.f, 0.f);
        #pragma unroll
        for (int j = 0; j < 8; j += 2) {
            int s0 = srcs[i + j], s1 = srcs[i + j + 1];
            float c0 = inv[s0] * invd, c1 = inv[s1] * invd;
            float4 v0 = *(const float4*)(h + (size_t)s0 * 128 + lane * 4);
            float4 v1 = *(const float4*)(h + (size_t)s1 * 128 + lane * 4);
            acc.x  += v0.x * c0; acc.y  += v0.y * c0; acc.z  += v0.z * c0; acc.w  += v0.w * c0;
            acc2.x += v1.x * c1; acc2.y += v1.y * c1; acc2.z += v1.z * c1; acc2.w += v1.w * c1;
        }
        acc.x += acc2.x; acc.y += acc2.y; acc.z += acc2.z; acc.w += acc2.w;
    }
    for (; i < end; i++) {
        int s = srcs[i];
        float c = inv[s] * invd;
        float4 v = *(const float4*)(h + (size_t)s * 128 + lane * 4);
        acc.x += v.x * c; acc.y += v.y * c; acc.z += v.z * c; acc.w += v.w * c;
    }
    float4 b = *(const float4*)&bias[lane * 4];
    acc.x = fmaxf(acc.x + b.x, 0.f); acc.y = fmaxf(acc.y + b.y, 0.f);
    acc.z = fmaxf(acc.z + b.z, 0.f); acc.w = fmaxf(acc.w + b.w, 0.f);
    *(float4*)(out + (size_t)d * 128 + lane * 4) = acc;
}

// ---------------- GAT scores ----------------
__global__ void k_gat_scores(const float* __restrict__ h2, const float* __restrict__ att_s,
                             const float* __restrict__ att_d, float* __restrict__ as_,
                             float* __restrict__ ad_, int n)
{
    int gid = blockIdx.x * blockDim.x + threadIdx.x;
    int w = gid >> 5, lane = gid & 31;
    if (w >= n * 2) return;
    int nn = w >> 1, hh = w & 1;
    const float* row = h2 + (size_t)nn * 128 + hh * 64;
    float v0 = row[lane], v1 = row[lane + 32];
    float s = v0 * att_s[hh * 64 + lane] + v1 * att_s[hh * 64 + lane + 32];
    float d = v0 * att_d[hh * 64 + lane] + v1 * att_d[hh * 64 + lane + 32];
    #pragma unroll
    for (int o = 16; o; o >>= 1) {
        s += __shfl_down_sync(0xffffffffu, s, o);
        d += __shfl_down_sync(0xffffffffu, d, o);
    }
    if (lane == 0) { as_[w] = s; ad_[w] = d; }
}

// ---------------- GAT fused softmax + aggregation + head-mean + elu, warp/node -------------
__global__ void k_gat_agg(const float* __restrict__ h2, const int* __restrict__ off,
                          const int* __restrict__ deg, const int* __restrict__ srcs,
                          const float* __restrict__ as_, const float* __restrict__ ad_,
                          const float* __restrict__ bg, float* __restrict__ hx, int n)
{
    int gid = blockIdx.x * blockDim.x + threadIdx.x;
    int d = gid >> 5, lane = gid & 31;
    if (d >= n) return;
    int beg = off[d], end = beg + deg[d];

    float2 ad = *(const float2*)(ad_ + d * 2);
    float2 asd = *(const float2*)(as_ + d * 2);
    float e0s = leaky(asd.x + ad.x), e1s = leaky(asd.y + ad.y);

    float m0 = e0s, m1 = e1s;
    for (int i = beg + lane; i < end; i += 32) {
        float2 a = *(const float2*)(as_ + srcs[i] * 2);
        m0 = fmaxf(m0, leaky(a.x + ad.x));
        m1 = fmaxf(m1, leaky(a.y + ad.y));
    }
    #pragma unroll
    for (int o = 16; o; o >>= 1) {
        m0 = fmaxf(m0, __shfl_xor_sync(0xffffffffu, m0, o));
        m1 = fmaxf(m1, __shfl_xor_sync(0xffffffffu, m1, o));
    }
    float den0 = 0.f, den1 = 0.f;
    for (int i = beg + lane; i < end; i += 32) {
        float2 a = *(const float2*)(as_ + srcs[i] * 2);
        den0 += __expf(leaky(a.x + ad.x) - m0);
        den1 += __expf(leaky(a.y + ad.y) - m1);
    }
    #pragma unroll
    for (int o = 16; o; o >>= 1) {
        den0 += __shfl_xor_sync(0xffffffffu, den0, o);
        den1 += __shfl_xor_sync(0xffffffffu, den1, o);
    }
    den0 += __expf(e0s - m0);
    den1 += __expf(e1s - m1);
    float r0 = __fdividef(1.f, den0), r1 = __fdividef(1.f, den1);

    float als = (lane < 16) ? __expf(e0s - m0) * r0 : __expf(e1s - m1) * r1;
    float4 sv = *(const float4*)(h2 + (size_t)d * 128 + lane * 4);
    float4 acc = make_float4(sv.x * als, sv.y * als, sv.z * als, sv.w * als);
    int i = beg;
    for (; i + 4 <= end; i += 4) {
        int s0 = srcs[i], s1 = srcs[i+1], s2 = srcs[i+2], s3 = srcs[i+3];
        float2 a0 = *(const float2*)(as_ + s0 * 2);
        float2 a1 = *(const float2*)(as_ + s1 * 2);
        float2 a2 = *(const float2*)(as_ + s2 * 2);
        float2 a3 = *(const float2*)(as_ + s3 * 2);
        bool h0 = lane < 16;
        float c0 = h0 ? __expf(leaky(a0.x + ad.x) - m0) * r0 : __expf(leaky(a0.y + ad.y) - m1) * r1;
        float c1 = h0 ? __expf(leaky(a1.x + ad.x) - m0) * r0 : __expf(leaky(a1.y + ad.y) - m1) * r1;
        float c2 = h0 ? __expf(leaky(a2.x + ad.x) - m0) * r0 : __expf(leaky(a2.y + ad.y) - m1) * r1;
        float c3 = h0 ? __expf(leaky(a3.x + ad.x) - m0) * r0 : __expf(leaky(a3.y + ad.y) - m1) * r1;
        float4 v0 = *(const float4*)(h2 + (size_t)s0 * 128 + lane * 4);
        float4 v1 = *(const float4*)(h2 + (size_t)s1 * 128 + lane * 4);
        float4 v2 = *(const float4*)(h2 + (size_t)s2 * 128 + lane * 4);
        float4 v3 = *(const float4*)(h2 + (size_t)s3 * 128 + lane * 4);
        acc.x += v0.x*c0 + v1.x*c1 + v2.x*c2 + v3.x*c3;
        acc.y += v0.y*c0 + v1.y*c1 + v2.y*c2 + v3.y*c3;
        acc.z += v0.z*c0 + v1.z*c1 + v2.z*c2 + v3.z*c3;
        acc.w += v0.w*c0 + v1.w*c1 + v2.w*c2 + v3.w*c3;
    }
    for (; i < end; i++) {
        int s = srcs[i];
        float2 a = *(const float2*)(as_ + s * 2);
        float c = (lane < 16) ? __expf(leaky(a.x + ad.x) - m0) * r0
                              : __expf(leaky(a.y + ad.y) - m1) * r1;
        float4 v = *(const float4*)(h2 + (size_t)s * 128 + lane * 4);
        acc.x += v.x * c; acc.y += v.y * c; acc.z += v.z * c; acc.w += v.w * c;
    }
    float ox = __shfl_down_sync(0xffffffffu, acc.x, 16);
    float oy = __shfl_down_sync(0xffffffffu, acc.y, 16);
    float oz = __shfl_down_sync(0xffffffffu, acc.z, 16);
    float ow = __shfl_down_sync(0xffffffffu, acc.w, 16);
    if (lane < 16) {
        float4 b = *(const float4*)&bg[lane * 4];
        float4 r;
        r.x = 0.5f * (acc.x + ox) + b.x;
        r.y = 0.5f * (acc.y + oy) + b.y;
        r.z = 0.5f * (acc.z + oz) + b.z;
        r.w = 0.5f * (acc.w + ow) + b.w;
        r.x = r.x > 0.f ? r.x : expm1f(r.x);
        r.y = r.y > 0.f ? r.y : expm1f(r.y);
        r.z = r.z > 0.f ? r.z : expm1f(r.z);
        r.w = r.w > 0.f ? r.w : expm1f(r.w);
        *(float4*)(hx + (size_t)d * 64 + lane * 4) = r;
    }
}

// ---------------- GCN2 pull-aggregation (F=64), warp/node, unroll-8 ----------------
__global__ void k_gcn2_agg(const float* __restrict__ h, const int* __restrict__ off,
                           const int* __restrict__ deg, const int* __restrict__ srcs,
                           const float* __restrict__ inv, const float* __restrict__ bias,
                           float* __restrict__ out, int n)
{
    int gid = blockIdx.x * blockDim.x + threadIdx.x;
    int d = gid >> 5, lane = gid & 31;
    if (d >= n) return;
    int beg = off[d], end = beg + deg[d];
    float invd = inv[d];

    float2 sv = *(const float2*)(h + (size_t)d * 64 + lane * 2);
    float cs = invd * invd;
    float2 acc = make_float2(sv.x * cs, sv.y * cs);

    int i = beg;
    for (; i + 8 <= end; i += 8) {
        float2 acc2 = make_float2(0.f, 0.f);
        #pragma unroll
        for (int j = 0; j < 8; j += 2) {
            int s0 = srcs[i + j], s1 = srcs[i + j + 1];
            float c0 = inv[s0] * invd, c1 = inv[s1] * invd;
            float2 v0 = *(const float2*)(h + (size_t)s0 * 64 + lane * 2);
            float2 v1 = *(const float2*)(h + (size_t)s1 * 64 + lane * 2);
            acc.x  += v0.x * c0; acc.y  += v0.y * c0;
            acc2.x += v1.x * c1; acc2.y += v1.y * c1;
        }
        acc.x += acc2.x; acc.y += acc2.y;
    }
    for (; i < end; i++) {
        int s = srcs[i];
        float c = inv[s] * invd;
        float2 v = *(const float2*)(h + (size_t)s * 64 + lane * 2);
        acc.x += v.x * c; acc.y += v.y * c;
    }
    float2 b = *(const float2*)&bias[lane * 2];
    *(float2*)(out + (size_t)d * 64 + lane * 2) = make_float2(acc.x + b.x, acc.y + b.y);
}

// ---------------- host ----------------
static inline int up(int a, int b) { return (a + b - 1) / b; }

extern "C" void kernel_launch(void* const* d_in, const int* in_sizes, int n_in,
                              void* d_out, int out_size)
{
    const float* x       = (const float*)d_in[0];
    const int*   ei      = (const int*)d_in[1];    // int32 (JAX x64 disabled)
    const float* W1      = (const float*)d_in[2];
    const float* b1      = (const float*)d_in[3];
    const float* Wg      = (const float*)d_in[4];
    const float* att_src = (const float*)d_in[5];
    const float* att_dst = (const float*)d_in[6];
    const float* bg      = (const float*)d_in[7];
    const float* W3      = (const float*)d_in[8];
    const float* b3      = (const float*)d_in[9];
    float* out = (float*)d_out;

    int n = in_sizes[0] / 128;
    int E = in_sizes[1] / 2;
    const int* src = ei;
    const int* dst = ei + E;

    void* p;
    cudaGetSymbolAddress(&p, g_h1);   float* h1    = (float*)p;
    cudaGetSymbolAddress(&p, g_agg);  float* agg   = (float*)p;
    cudaGetSymbolAddress(&p, g_inv);  float* inv   = (float*)p;
    cudaGetSymbolAddress(&p, g_as);   float* as_   = (float*)p;
    cudaGetSymbolAddress(&p, g_ad);   float* ad_   = (float*)p;
    cudaGetSymbolAddress(&p, g_hx);   float* hx    = (float*)p;
    cudaGetSymbolAddress(&p, g_h3);   float* h3    = (float*)p;
    cudaGetSymbolAddress(&p, g_deg);  int*   deg   = (int*)p;
    cudaGetSymbolAddress(&p, g_off);  int*   off   = (int*)p;
    cudaGetSymbolAddress(&p, g_cur);  int*   cur   = (int*)p;
    cudaGetSymbolAddress(&p, g_srcs); int*   srcs  = (int*)p;
    cudaGetSymbolAddress(&p, g_total); unsigned* total = (unsigned*)p;

    // fork-join side stream for CSR build (created once; capture-safe pattern)
    static cudaStream_t s2 = nullptr;
    static cudaEvent_t evFork = nullptr, evJoin = nullptr;
    if (!s2) {
        cudaStreamCreateWithFlags(&s2, cudaStreamNonBlocking);
        cudaEventCreateWithFlags(&evFork, cudaEventDisableTiming);
        cudaEventCreateWithFlags(&evJoin, cudaEventDisableTiming);
    }

    const int T = 256;

    // ---- fork: CSR build on s2, GEMM1 on default ----
    cudaEventRecord(evFork, 0);
    cudaStreamWaitEvent(s2, evFork, 0);

    k_zero_deg <<<up(n, T), T, 0, s2>>>(deg, total, n);
    k_deg_count<<<up(E, T), T, 0, s2>>>(dst, deg, E);
    k_offsets  <<<up(n, T), T, 0, s2>>>(deg, off, cur, inv, total, n);
    k_fill     <<<up(E, T * 4), T, 0, s2>>>(src, dst, cur, srcs, E);
    cudaEventRecord(evJoin, s2);

    gemm_tf32<128,128><<<up(n, 128), 256>>>(x, W1, h1, n);

    cudaStreamWaitEvent(0, evJoin, 0);   // join before first aggregation

    // ---- GCN layer 1 ----
    k_gcn1_agg<<<up(n * 32, T), T>>>(h1, off, deg, srcs, inv, b1, agg, n);

    // ---- GAT layer ----
    gemm_tf32<128,128><<<up(n, 128), 256>>>(agg, Wg, h1, n);   // h2 in h1
    k_gat_scores<<<up(n * 64, T), T>>>(h1, att_src, att_dst, as_, ad_, n);
    k_gat_agg   <<<up(n * 32, T), T>>>(h1, off, deg, srcs, as_, ad_, bg, hx, n);

    // ---- GCN layer 2 ----
    gemm_tf32<64,64><<<up(n, 128), 256>>>(hx, W3, h3, n);
    k_gcn2_agg<<<up(n * 32, T), T>>>(h3, off, deg, srcs, inv, b3, out, n);
}